// round 10
// baseline (speedup 1.0000x reference)
#include <cuda_runtime.h>

// SSIM loss, fused separable, packed f32x2 math.
// Key change vs prior rounds: 256-thread blocks, 2 blocks/SM (two independent
// barrier domains per SM) so per-row __syncthreads stalls in one block are
// filled by the other block's warps.
// pred, gt: f32 [16,3,512,512] -> out: f32 scalar = 1 - mean(ssim_map)

#define IMG_H 512
#define IMG_W 512
#define N_IMG 48
#define TH 64
#define NROWS (TH + 10)          // 74 input rows per strip
#define NITER 77                 // 7*11: ring period 11 -> const-folded slots
#define SPAD 8
#define CW 256                   // columns per block (half a row)
#define SW2 (CW + 2 * SPAD)      // 272
#define NSTRIPS (IMG_H / TH)     // 8
#define NHALF 2
#define NBLK (N_IMG * NSTRIPS * NHALF)   // 768
#define C1F 0.0001f
#define C2F 0.0009f

#define GW0 0.00102838f
#define GW1 0.00759876f
#define GW2 0.03600078f
#define GW3 0.10936069f
#define GW4 0.21300553f
#define GW5 0.26601172f

__device__ float        g_partials[NBLK];
__device__ unsigned int g_count;      // zero-init; last block re-arms it

typedef unsigned long long u64;

static __device__ __forceinline__ u64 pack2(float lo, float hi) {
    u64 r; asm("mov.b64 %0, {%1, %2};" : "=l"(r) : "f"(lo), "f"(hi)); return r;
}
static __device__ __forceinline__ void unpack2(u64 v, float& lo, float& hi) {
    asm("mov.b64 {%0, %1}, %2;" : "=f"(lo), "=f"(hi) : "l"(v));
}
static __device__ __forceinline__ u64 fma2(u64 a, u64 b, u64 c) {
    u64 d; asm("fma.rn.f32x2 %0, %1, %2, %3;" : "=l"(d) : "l"(a), "l"(b), "l"(c)); return d;
}
static __device__ __forceinline__ u64 mul2(u64 a, u64 b) {
    u64 d; asm("mul.rn.f32x2 %0, %1, %2;" : "=l"(d) : "l"(a), "l"(b)); return d;
}

__global__ __launch_bounds__(256, 2)
void ssim_main(const float* __restrict__ pred, const float* __restrict__ gt,
               float* __restrict__ out)
{
    __shared__ u64   s2[2][SW2];      // packed (x,y) rows, double buffered
    __shared__ float sred[8];
    __shared__ unsigned int s_last;

    const float Wt[6] = {GW0, GW1, GW2, GW3, GW4, GW5};
    u64 W2[6];
    #pragma unroll
    for (int i = 0; i < 6; ++i) W2[i] = pack2(Wt[i], Wt[i]);

    const int c     = threadIdx.x;            // one thread per output column
    const int bx    = blockIdx.x;             // 0..15
    const int strip = bx >> 1;
    const int half  = bx & 1;
    const int img   = blockIdx.y;
    const int bid   = img * (NSTRIPS * NHALF) + bx;
    const int row0  = strip * TH;
    const int gc0   = half * CW;
    const int gc    = gc0 + c;                // this thread's global column
    const float* px = pred + (size_t)img * (IMG_H * IMG_W);
    const float* py = gt   + (size_t)img * (IMG_H * IMG_W);

    // halo duty for threads 0..15 (real neighbor data on the interior edge)
    const bool hasHalo = (c < 16);
    const int  hcol = (c < 8) ? (gc0 - 8 + c) : (gc0 + CW + (c - 8));   // global col
    const int  hidx = (c < 8) ? c : (SPAD + CW + (c - 8));              // smem idx

    // vertical ring: packed (mu1,mu2), packed (Exx,Eyy), scalar Exy
    u64 amu[11], avar[11]; float axy[11];
    #pragma unroll
    for (int j = 0; j < 11; ++j) { amu[j] = 0ULL; avar[j] = 0ULL; axy[j] = 0.f; }

    // preload input row 0 (global row row0-5)
    float xc = 0.f, yc = 0.f, xh = 0.f, yh = 0.f;
    {
        const int gr = row0 - 5;
        if ((unsigned)gr < IMG_H) {
            xc = px[gr * IMG_W + gc];
            yc = py[gr * IMG_W + gc];
            if (hasHalo && (unsigned)hcol < IMG_W) {
                xh = px[gr * IMG_W + hcol];
                yh = py[gr * IMG_W + hcol];
            }
        }
    }

    float tsum = 0.f;

    #pragma unroll 1
    for (int rb = 0; rb < NITER; rb += 11) {
        #pragma unroll
        for (int i = 0; i < 11; ++i) {        // rb%11==0 -> ring slots fold
            const int r = rb + i;
            const int b = r & 1;

            s2[b][SPAD + c] = pack2(xc, yc);
            if (hasHalo) s2[b][hidx] = pack2(xh, yh);
            __syncthreads();

            // prefetch next row under this row's compute
            float xn = 0.f, yn = 0.f, xhn = 0.f, yhn = 0.f;
            {
                const int gr = row0 - 5 + r + 1;
                if ((r + 1 < NROWS) && ((unsigned)gr < IMG_H)) {
                    xn = px[gr * IMG_W + gc];
                    yn = py[gr * IMG_W + gc];
                    if (hasHalo && (unsigned)hcol < IMG_W) {
                        xhn = px[gr * IMG_W + hcol];
                        yhn = py[gr * IMG_W + hcol];
                    }
                }
            }

            // horizontal 11-tap conv: packed mu / packed var, scalar xy
            u64 hmu = 0ULL, hvar = 0ULL; float hxy = 0.f;
            #pragma unroll
            for (int k = 0; k < 11; ++k) {
                const int wi = (k < 6) ? k : 10 - k;
                const u64 p = s2[b][SPAD - 5 + c + k];   // LDS.64 (x,y)
                hmu  = fma2(p, W2[wi], hmu);
                hvar = fma2(mul2(p, p), W2[wi], hvar);
                float pl, ph; unpack2(p, pl, ph);        // reg aliases, no-op
                hxy = fmaf(Wt[wi], pl * ph, hxy);        // FMUL + FFMA-imm
            }

            // vertical scatter into ring (slot indices constant-folded)
            #pragma unroll
            for (int j = 0; j < 11; ++j) {
                const int s  = (i + 1 + j) % 11;
                const int wi = (j < 6) ? j : 10 - j;
                amu[s]  = fma2(hmu,  W2[wi], amu[s]);
                avar[s] = fma2(hvar, W2[wi], avar[s]);
                axy[s]  = fmaf(Wt[wi], hxy, axy[s]);
            }

            // slot (i+1)%11 completed -> output row r-10
            const int s0 = (i + 1) % 11;
            const int o  = r - 10;
            if (o >= 0 && o < TH) {
                float mu1, mu2, Exx, Eyy;
                unpack2(amu[s0], mu1, mu2);
                unpack2(avar[s0], Exx, Eyy);
                const float m11 = mu1 * mu1;
                const float m22 = mu2 * mu2;
                const float m12 = mu1 * mu2;
                const float v1  = Exx - m11;
                const float v2  = Eyy - m22;
                const float v12 = axy[s0] - m12;
                const float num = (2.f * m12 + C1F) * (2.f * v12 + C2F);
                const float den = (m11 + m22 + C1F) * (v1 + v2 + C2F);
                tsum += __fdividef(num, den);
            }
            amu[s0] = 0ULL; avar[s0] = 0ULL; axy[s0] = 0.f;

            xc = xn; yc = yn; xh = xhn; yh = yhn;
        }
    }

    // deterministic block reduction (8 warps)
    #pragma unroll
    for (int off = 16; off > 0; off >>= 1)
        tsum += __shfl_down_sync(0xffffffffu, tsum, off);
    if ((c & 31) == 0) sred[c >> 5] = tsum;
    __syncthreads();
    if (c == 0) {
        float s = 0.f;
        #pragma unroll
        for (int w = 0; w < 8; ++w) s += sred[w];
        g_partials[bid] = s;
        __threadfence();
        const unsigned int old = atomicAdd(&g_count, 1u);
        s_last = (old == NBLK - 1) ? 1u : 0u;
    }
    __syncthreads();

    // last-finishing block reduces the 768 partials (fixed order -> deterministic)
    if (s_last) {
        float v = __ldcg(&g_partials[c])
                + __ldcg(&g_partials[c + 256])
                + __ldcg(&g_partials[c + 512]);
        #pragma unroll
        for (int off = 16; off > 0; off >>= 1)
            v += __shfl_down_sync(0xffffffffu, v, off);
        if ((c & 31) == 0) sred[c >> 5] = v;
        __syncthreads();
        if (c == 0) {
            float s = 0.f;
            #pragma unroll
            for (int w = 0; w < 8; ++w) s += sred[w];
            out[0] = 1.0f - s * (1.0f / 12582912.0f);
            g_count = 0;              // re-arm for next graph replay
        }
    }
}

extern "C" void kernel_launch(void* const* d_in, const int* in_sizes, int n_in,
                              void* d_out, int out_size)
{
    (void)in_sizes; (void)n_in; (void)out_size;
    const float* pred = (const float*)d_in[0];
    const float* gt   = (const float*)d_in[1];

    dim3 grid(NSTRIPS * NHALF, N_IMG);        // (16, 48) = 768 blocks
    ssim_main<<<grid, CW>>>(pred, gt, (float*)d_out);
}

// round 11
// speedup vs baseline: 1.2232x; 1.2232x over previous
#include <cuda_runtime.h>

// SSIM loss, fused separable, WARP-AUTONOMOUS tiles (no __syncthreads in the
// main loop). Each warp owns a 32-column strip + warp-private smem row buffer
// (42 cols incl. +-5 halo, double buffered, __syncwarp only). Math tuned for
// sm_103a pipe rates: mul.f32x2 for squares, FFMA-imm (rt=1) for all
// accumulating chains.
// pred, gt: f32 [16,3,512,512] -> out: f32 scalar = 1 - mean(ssim_map)

#define IMG_H 512
#define IMG_W 512
#define N_IMG 48
#define TH 64
#define NROWS (TH + 10)          // 74 input rows per strip
#define NITER 77                 // 7*11: ring slot indices constant-fold
#define NSTRIPS (IMG_H / TH)     // 8
#define NBLK (N_IMG * NSTRIPS)   // 384
#define NWARP 16
#define BUFW 44                  // 42 used, padded
#define C1F 0.0001f
#define C2F 0.0009f

#define GW0 0.00102838f
#define GW1 0.00759876f
#define GW2 0.03600078f
#define GW3 0.10936069f
#define GW4 0.21300553f
#define GW5 0.26601172f

__device__ float        g_partials[NBLK];
__device__ unsigned int g_count;          // zero-init; last block re-arms

typedef unsigned long long u64;

static __device__ __forceinline__ u64 pack2(float lo, float hi) {
    u64 r; asm("mov.b64 %0, {%1, %2};" : "=l"(r) : "f"(lo), "f"(hi)); return r;
}
static __device__ __forceinline__ void unpack2(u64 v, float& lo, float& hi) {
    asm("mov.b64 {%0, %1}, %2;" : "=f"(lo), "=f"(hi) : "l"(v));
}
static __device__ __forceinline__ u64 mul2(u64 a, u64 b) {
    u64 d; asm("mul.rn.f32x2 %0, %1, %2;" : "=l"(d) : "l"(a), "l"(b)); return d;
}

__global__ __launch_bounds__(512, 1)
void ssim_main(const float* __restrict__ pred, const float* __restrict__ gt,
               float* __restrict__ out)
{
    __shared__ float2 buf[NWARP][2][BUFW];   // warp-private, double buffered
    __shared__ float  sred[NWARP];
    __shared__ unsigned int s_last;

    const float Wt[11] = {GW0, GW1, GW2, GW3, GW4, GW5, GW4, GW3, GW2, GW1, GW0};

    const int tid   = threadIdx.x;
    const int w     = tid >> 5;              // warp id: column tile
    const int c     = tid & 31;              // lane
    const int strip = blockIdx.x;
    const int img   = blockIdx.y;
    const int bid   = img * NSTRIPS + strip;
    const int row0  = strip * TH;
    const float* px = pred + (size_t)img * (IMG_H * IMG_W);
    const float* py = gt   + (size_t)img * (IMG_H * IMG_W);

    // column assignment: warp covers output cols [w0, w0+32); buffer index k
    // maps to input col w0-5+k, k in [0,42)
    const int  w0   = w * 32;
    const int  gm   = w0 - 5 + c;            // main load col (buf idx c)
    const int  gh   = w0 + 27 + c;           // halo load col (buf idx 32+c), c<10
    const bool vm   = (unsigned)gm < IMG_W;
    const bool isH  = (c < 10);
    const bool vh   = isH && ((unsigned)gh < IMG_W);

    // vertical ring: 5 quantities x 11 slots, scalar (FFMA-imm vertical)
    float a1[11], a2[11], a3[11], a4[11], a5[11];
    #pragma unroll
    for (int j = 0; j < 11; ++j) { a1[j]=0.f; a2[j]=0.f; a3[j]=0.f; a4[j]=0.f; a5[j]=0.f; }

    // preload input row 0 (global row row0-5)
    float xm = 0.f, ym = 0.f, xh = 0.f, yh = 0.f;
    {
        const int gr = row0 - 5;
        if ((unsigned)gr < IMG_H) {
            const int o = gr * IMG_W;
            if (vm) { xm = px[o + gm]; ym = py[o + gm]; }
            if (vh) { xh = px[o + gh]; yh = py[o + gh]; }
        }
    }

    float tsum = 0.f;

    #pragma unroll 1
    for (int rb = 0; rb < NITER; rb += 11) {
        #pragma unroll
        for (int i = 0; i < 11; ++i) {       // rb%11==0 -> ring slots fold
            const int r  = rb + i;
            const int st = r & 1;

            buf[w][st][c] = make_float2(xm, ym);
            if (isH) buf[w][st][32 + c] = make_float2(xh, yh);
            __syncwarp();

            // prefetch next row under this row's compute (warp-independent)
            float xn = 0.f, yn = 0.f, xhn = 0.f, yhn = 0.f;
            {
                const int gr = row0 - 5 + r + 1;
                if ((r + 1 < NROWS) && ((unsigned)gr < IMG_H)) {
                    const int o = gr * IMG_W;
                    if (vm) { xn  = px[o + gm]; yn  = py[o + gm]; }
                    if (vh) { xhn = px[o + gh]; yhn = py[o + gh]; }
                }
            }

            // horizontal 11-tap conv: mul2 for squares, FFMA-imm accumulate
            float hx = 0.f, hy = 0.f, hxx = 0.f, hyy = 0.f, hxy = 0.f;
            #pragma unroll
            for (int k = 0; k < 11; ++k) {
                const float2 p = buf[w][st][c + k];      // LDS.64
                const float wk = Wt[k];                  // literal -> imm
                const u64 P  = pack2(p.x, p.y);
                const u64 PP = mul2(P, P);               // (x*x, y*y) in 1 op
                float sx2, sy2; unpack2(PP, sx2, sy2);
                hx  = fmaf(p.x,       wk, hx);
                hy  = fmaf(p.y,       wk, hy);
                hxx = fmaf(sx2,       wk, hxx);
                hyy = fmaf(sy2,       wk, hyy);
                hxy = fmaf(p.x * p.y, wk, hxy);
            }

            // vertical scatter into ring (indices constant-folded, FFMA-imm)
            #pragma unroll
            for (int j = 0; j < 11; ++j) {
                const int   s  = (i + 1 + j) % 11;
                const float wv = Wt[10 - j];             // literal -> imm
                a1[s] = fmaf(hx,  wv, a1[s]);
                a2[s] = fmaf(hy,  wv, a2[s]);
                a3[s] = fmaf(hxx, wv, a3[s]);
                a4[s] = fmaf(hyy, wv, a4[s]);
                a5[s] = fmaf(hxy, wv, a5[s]);
            }

            // slot (i+1)%11 completed -> output row r-10
            const int s0 = (i + 1) % 11;
            const int o  = r - 10;
            if (o >= 0 && o < TH) {
                const float mu1 = a1[s0], mu2 = a2[s0];
                const float m11 = mu1 * mu1;
                const float m22 = mu2 * mu2;
                const float m12 = mu1 * mu2;
                const float v1  = a3[s0] - m11;
                const float v2  = a4[s0] - m22;
                const float v12 = a5[s0] - m12;
                const float num = (2.f * m12 + C1F) * (2.f * v12 + C2F);
                const float den = (m11 + m22 + C1F) * (v1 + v2 + C2F);
                tsum += __fdividef(num, den);
            }
            a1[s0]=0.f; a2[s0]=0.f; a3[s0]=0.f; a4[s0]=0.f; a5[s0]=0.f;

            xm = xn; ym = yn; xh = xhn; yh = yhn;
        }
    }

    // block reduction (first and only __syncthreads)
    #pragma unroll
    for (int off = 16; off > 0; off >>= 1)
        tsum += __shfl_down_sync(0xffffffffu, tsum, off);
    if (c == 0) sred[w] = tsum;
    __syncthreads();
    if (tid == 0) {
        float s = 0.f;
        #pragma unroll
        for (int k = 0; k < NWARP; ++k) s += sred[k];
        g_partials[bid] = s;
        __threadfence();
        const unsigned int old = atomicAdd(&g_count, 1u);
        s_last = (old == NBLK - 1) ? 1u : 0u;
    }
    __syncthreads();

    // last-finishing block reduces the 384 partials (fixed order, deterministic)
    if (s_last) {
        float v = (tid < NBLK) ? __ldcg(&g_partials[tid]) : 0.f;
        #pragma unroll
        for (int off = 16; off > 0; off >>= 1)
            v += __shfl_down_sync(0xffffffffu, v, off);
        if (c == 0) sred[w] = v;
        __syncthreads();
        if (tid == 0) {
            float s = 0.f;
            #pragma unroll
            for (int k = 0; k < NWARP; ++k) s += sred[k];
            out[0] = 1.0f - s * (1.0f / 12582912.0f);
            g_count = 0;                     // re-arm for next graph replay
        }
    }
}

extern "C" void kernel_launch(void* const* d_in, const int* in_sizes, int n_in,
                              void* d_out, int out_size)
{
    (void)in_sizes; (void)n_in; (void)out_size;
    const float* pred = (const float*)d_in[0];
    const float* gt   = (const float*)d_in[1];

    dim3 grid(NSTRIPS, N_IMG);               // (8, 48) = 384 blocks
    ssim_main<<<grid, 512>>>(pred, gt, (float*)d_out);
}

// round 12
// speedup vs baseline: 1.7666x; 1.4443x over previous
#include <cuda_runtime.h>

// SSIM loss, fused separable. R3 scalar-imm body (best known) + makespan-
// balanced grid: 6 strips/image (5x TH=89, 1x TH=67; both NITER = TH+10 are
// multiples of 11 so ring-slot indices constant-fold). 288 blocks -> two
// near-full waves on 148 SMs (worst SM 198 row-iters vs 231 before).
// pred, gt: f32 [16,3,512,512] -> out: f32 scalar = 1 - mean(ssim_map)

#define IMG_H 512
#define IMG_W 512
#define N_IMG 48
#define NSTRIP 6
#define NBLK (N_IMG * NSTRIP)     // 288
#define SPAD 8
#define SW (IMG_W + 2 * SPAD)     // 528
#define C1F 0.0001f
#define C2F 0.0009f

#define GW0 0.00102838f
#define GW1 0.00759876f
#define GW2 0.03600078f
#define GW3 0.10936069f
#define GW4 0.21300553f
#define GW5 0.26601172f

__device__ float        g_partials[NBLK];
__device__ unsigned int g_count;          // zero-init; last block re-arms

// One strip: THT output rows, NITERT = THT+10 input rows, NITERT % 11 == 0.
template<int THT, int NITERT>
static __device__ __forceinline__
float strip_body(const float* __restrict__ px, const float* __restrict__ py,
                 const int row0, const int c, float2 (&s2)[2][SW])
{
    const float Wt[11] = {GW0, GW1, GW2, GW3, GW4, GW5, GW4, GW3, GW2, GW1, GW0};

    // vertical ring: 5 quantities x 11 slots, all registers
    float a1[11], a2[11], a3[11], a4[11], a5[11];
    #pragma unroll
    for (int j = 0; j < 11; ++j) { a1[j]=0.f; a2[j]=0.f; a3[j]=0.f; a4[j]=0.f; a5[j]=0.f; }

    // preload input row 0 (global row row0-5)
    float xc = 0.f, yc = 0.f;
    {
        const int gr = row0 - 5;
        if ((unsigned)gr < IMG_H) { xc = px[gr * IMG_W + c]; yc = py[gr * IMG_W + c]; }
    }

    float tsum = 0.f;

    #pragma unroll 1
    for (int rb = 0; rb < NITERT; rb += 11) {
        #pragma unroll
        for (int i = 0; i < 11; ++i) {        // rb%11==0 -> ring slots fold
            const int r = rb + i;
            const int b = r & 1;

            s2[b][SPAD + c] = make_float2(xc, yc);
            __syncthreads();

            // prefetch next row under this row's compute
            float xn = 0.f, yn = 0.f;
            {
                const int gr = row0 - 5 + r + 1;
                if ((r + 1 < NITERT) && ((unsigned)gr < IMG_H)) {
                    xn = px[gr * IMG_W + c];
                    yn = py[gr * IMG_W + c];
                }
            }

            // horizontal 11-tap conv of 5 quantities (weights -> FFMA-imm)
            float hx = 0.f, hy = 0.f, hxx = 0.f, hyy = 0.f, hxy = 0.f;
            #pragma unroll
            for (int k = 0; k < 11; ++k) {
                const float2 p = s2[b][SPAD - 5 + c + k];   // LDS.64
                hx  = fmaf(p.x,       Wt[k], hx);
                hy  = fmaf(p.y,       Wt[k], hy);
                hxx = fmaf(p.x * p.x, Wt[k], hxx);
                hyy = fmaf(p.y * p.y, Wt[k], hyy);
                hxy = fmaf(p.x * p.y, Wt[k], hxy);
            }

            // vertical scatter into ring (slot indices constant-folded)
            #pragma unroll
            for (int j = 0; j < 11; ++j) {
                const int   s  = (i + 1 + j) % 11;
                const float wv = Wt[10 - j];                // literal -> imm
                a1[s] = fmaf(hx,  wv, a1[s]);
                a2[s] = fmaf(hy,  wv, a2[s]);
                a3[s] = fmaf(hxx, wv, a3[s]);
                a4[s] = fmaf(hyy, wv, a4[s]);
                a5[s] = fmaf(hxy, wv, a5[s]);
            }

            // slot (i+1)%11 completed -> output row r-10
            const int s0 = (i + 1) % 11;
            const int o  = r - 10;
            if (o >= 0 && o < THT) {
                const float mu1 = a1[s0], mu2 = a2[s0];
                const float m11 = mu1 * mu1;
                const float m22 = mu2 * mu2;
                const float m12 = mu1 * mu2;
                const float v1  = a3[s0] - m11;
                const float v2  = a4[s0] - m22;
                const float v12 = a5[s0] - m12;
                const float num = (2.f * m12 + C1F) * (2.f * v12 + C2F);
                const float den = (m11 + m22 + C1F) * (v1 + v2 + C2F);
                tsum += __fdividef(num, den);
            }
            a1[s0]=0.f; a2[s0]=0.f; a3[s0]=0.f; a4[s0]=0.f; a5[s0]=0.f;

            xc = xn; yc = yn;
        }
    }
    return tsum;
}

__global__ __launch_bounds__(512, 1)
void ssim_main(const float* __restrict__ pred, const float* __restrict__ gt,
               float* __restrict__ out)
{
    __shared__ float2 s2[2][SW];           // packed (x,y) rows, double buffered
    __shared__ float  sred[16];
    __shared__ unsigned int s_last;

    const int c     = threadIdx.x;         // one thread per column
    const int strip = blockIdx.x;          // 0..5
    const int img   = blockIdx.y;
    const int bid   = img * NSTRIP + strip;
    const float* px = pred + (size_t)img * (IMG_H * IMG_W);
    const float* py = gt   + (size_t)img * (IMG_H * IMG_W);

    // zero column halos (stay zero; first-iteration barrier orders them)
    if (c < SPAD) {
        const float2 z = make_float2(0.f, 0.f);
        s2[0][c] = z; s2[1][c] = z;
        s2[0][SPAD + IMG_W + c] = z; s2[1][SPAD + IMG_W + c] = z;
    }

    float tsum;
    if (strip < 5) tsum = strip_body<89, 99>(px, py, strip * 89, c, s2);
    else           tsum = strip_body<67, 77>(px, py, 445,        c, s2);

    // deterministic block reduction
    #pragma unroll
    for (int off = 16; off > 0; off >>= 1)
        tsum += __shfl_down_sync(0xffffffffu, tsum, off);
    if ((c & 31) == 0) sred[c >> 5] = tsum;
    __syncthreads();
    if (c == 0) {
        float s = 0.f;
        #pragma unroll
        for (int w = 0; w < 16; ++w) s += sred[w];
        g_partials[bid] = s;
        __threadfence();
        const unsigned int old = atomicAdd(&g_count, 1u);
        s_last = (old == NBLK - 1) ? 1u : 0u;
    }
    __syncthreads();

    // last-finishing block reduces the 288 partials (fixed order, deterministic)
    if (s_last) {
        float v = (c < NBLK) ? __ldcg(&g_partials[c]) : 0.f;
        #pragma unroll
        for (int off = 16; off > 0; off >>= 1)
            v += __shfl_down_sync(0xffffffffu, v, off);
        if ((c & 31) == 0) sred[c >> 5] = v;
        __syncthreads();
        if (c == 0) {
            float s = 0.f;
            #pragma unroll
            for (int w = 0; w < 16; ++w) s += sred[w];
            out[0] = 1.0f - s * (1.0f / 12582912.0f);
            g_count = 0;                   // re-arm for next graph replay
        }
    }
}

extern "C" void kernel_launch(void* const* d_in, const int* in_sizes, int n_in,
                              void* d_out, int out_size)
{
    (void)in_sizes; (void)n_in; (void)out_size;
    const float* pred = (const float*)d_in[0];
    const float* gt   = (const float*)d_in[1];

    dim3 grid(NSTRIP, N_IMG);              // (6, 48) = 288 blocks, 2 waves
    ssim_main<<<grid, IMG_W>>>(pred, gt, (float*)d_out);
}